// round 4
// baseline (speedup 1.0000x reference)
#include <cuda_runtime.h>
#include <cstdint>

// Problem shape (fixed by the dataset)
#define NMAX 50000
#define EMAX 1600000
#define D    128

// Scratch (static __device__ — no allocation allowed)
__device__ int   g_is64;                // edge_index element width flag
__device__ int   g_deg[NMAX];           // in-degree histogram
__device__ int   g_rowstart[NMAX];      // bucket start per dst
__device__ int   g_rowend[NMAX];        // bucket end per dst
__device__ int   g_cursor[NMAX];        // fill cursors
__device__ int   g_total;               // global bucket allocator
__device__ int   g_esrc[EMAX];          // CSR: src node per incoming edge
__device__ float g_inv[NMAX];           // 1/||x_i|| (clamped)

// ---------------------------------------------------------------------------
// index helpers (handle int32 or int64 edge_index)
// ---------------------------------------------------------------------------
__device__ __forceinline__ int ld_src(const void* p, int e, int is64) {
    if (is64) return (int)((const long long*)p)[e];
    return ((const int*)p)[e];
}
__device__ __forceinline__ int ld_dst(const void* p, int e, int E, int is64) {
    if (is64) return (int)((const long long*)p)[(long long)E + e];
    return ((const int*)p)[E + e];
}

// ---------------------------------------------------------------------------
// K0: detect int32 vs int64 edge_index. Values < 50000, so if int64 every odd
// 32-bit word of the first 32 entries is 0; random int32 makes that impossible.
// ---------------------------------------------------------------------------
__global__ void k_detect(const unsigned int* __restrict__ w) {
    int is64 = 1;
    #pragma unroll
    for (int i = 1; i < 64; i += 2)
        if (w[i] != 0u) { is64 = 0; break; }
    g_is64 = is64;
}

// ---------------------------------------------------------------------------
// K1: zero degree histogram + allocator
// ---------------------------------------------------------------------------
__global__ void k_zero(int N) {
    int i = blockIdx.x * blockDim.x + threadIdx.x;
    if (i < N) g_deg[i] = 0;
    if (i == 0) g_total = 0;
}

// ---------------------------------------------------------------------------
// K2: degree histogram over destinations
// ---------------------------------------------------------------------------
__global__ void k_hist(const void* __restrict__ idx, int E) {
    int e = blockIdx.x * blockDim.x + threadIdx.x;
    if (e >= E) return;
    int dst = ld_dst(idx, e, E, g_is64);
    atomicAdd(&g_deg[dst], 1);
}

// ---------------------------------------------------------------------------
// K3: decoupled bucket allocation. Per-block scan of 256 degrees (shuffle +
// shared), one global atomicAdd per block for the base. Bucket placement
// order is irrelevant to the output (gather only reads its own range).
// ---------------------------------------------------------------------------
__global__ void k_alloc(int N) {
    int i = blockIdx.x * blockDim.x + threadIdx.x;
    int lane = threadIdx.x & 31;
    int wid  = threadIdx.x >> 5;
    int d = (i < N) ? g_deg[i] : 0;

    // warp inclusive scan
    int v = d;
    #pragma unroll
    for (int o = 1; o < 32; o <<= 1) {
        int t = __shfl_up_sync(0xffffffffu, v, o);
        if (lane >= o) v += t;
    }

    __shared__ int wsum[8];
    __shared__ int base;
    if (lane == 31) wsum[wid] = v;
    __syncthreads();
    if (threadIdx.x == 0) {
        int tot = 0;
        #pragma unroll
        for (int k = 0; k < 8; k++) { int t = wsum[k]; wsum[k] = tot; tot += t; }
        base = atomicAdd(&g_total, tot);
    }
    __syncthreads();

    int start = base + wsum[wid] + v - d;   // exclusive prefix within block
    if (i < N) {
        g_rowstart[i] = start;
        g_cursor[i]   = start;
        g_rowend[i]   = start + d;
    }
}

// ---------------------------------------------------------------------------
// K4: CSR fill — scatter src ids into per-dst buckets
// ---------------------------------------------------------------------------
__global__ void k_fill(const void* __restrict__ idx, int E) {
    int e = blockIdx.x * blockDim.x + threadIdx.x;
    if (e >= E) return;
    int is64 = g_is64;
    int src = ld_src(idx, e, is64);
    int dst = ld_dst(idx, e, E, is64);
    int p = atomicAdd(&g_cursor[dst], 1);
    g_esrc[p] = src;
}

// ---------------------------------------------------------------------------
// K5: inverse norms. One warp per node row; float4 per lane.
// ---------------------------------------------------------------------------
__global__ void k_invnorm(const float* __restrict__ x, int N) {
    int w = (blockIdx.x * blockDim.x + threadIdx.x) >> 5;
    if (w >= N) return;
    int lane = threadIdx.x & 31;
    float4 v = ((const float4*)x)[w * 32 + lane];
    float ss = v.x * v.x + v.y * v.y + v.z * v.z + v.w * v.w;
    #pragma unroll
    for (int o = 16; o; o >>= 1) ss += __shfl_xor_sync(0xffffffffu, ss, o);
    if (lane == 0)
        g_inv[w] = rsqrtf(fmaxf(ss, 1e-24f));   // EPS^2 = (1e-12)^2
}

// ---------------------------------------------------------------------------
// K6: fused gather. One warp per destination node:
//   out[i] = relu( (Σ_e w_e x_src + w_self x_i) / (Σ_e w_e + w_self) )
//   w_e = exp(beta * cos(x_src, x_i) - |beta|)   (shift-invariant softmax)
// 2-way edge interleave: two independent dot/shuffle/exp chains per iteration
// to overlap the 5-deep SHFL latency and double rows in flight.
// ---------------------------------------------------------------------------
__global__ void k_gather(const float* __restrict__ x,
                         const float* __restrict__ beta,
                         float* __restrict__ out, int N) {
    int i = (blockIdx.x * blockDim.x + threadIdx.x) >> 5;
    if (i >= N) return;
    int lane = threadIdx.x & 31;

    const float4* X = (const float4*)x;
    float bta = beta[0];
    float B = fabsf(bta);

    float4 a = X[i * 32 + lane];

    // self-loop term (also yields inv_i locally — same formula as k_invnorm)
    float ss = a.x * a.x + a.y * a.y + a.z * a.z + a.w * a.w;
    #pragma unroll
    for (int o = 16; o; o >>= 1) ss += __shfl_xor_sync(0xffffffffu, ss, o);
    float inv_i = rsqrtf(fmaxf(ss, 1e-24f));
    float wv = __expf(bta * (ss * inv_i * inv_i) - B);
    float sum = wv;
    float4 acc = make_float4(wv * a.x, wv * a.y, wv * a.z, wv * a.w);

    int start = g_rowstart[i];
    int end   = g_rowend[i];

    float4 v0 = make_float4(0.f, 0.f, 0.f, 0.f);
    float4 v1 = v0;
    float  n0 = 0.f, n1 = 0.f;
    if (start < end)     { int s = g_esrc[start];     v0 = X[s * 32 + lane]; n0 = g_inv[s]; }
    if (start + 1 < end) { int s = g_esrc[start + 1]; v1 = X[s * 32 + lane]; n1 = g_inv[s]; }

    for (int j = start; j < end; j += 2) {
        float4 c0 = v0, c1 = v1;
        float  m0 = n0, m1 = n1;
        // prefetch next pair before the dependent reduce chains
        if (j + 2 < end) { int s = g_esrc[j + 2]; v0 = X[s * 32 + lane]; n0 = g_inv[s]; }
        if (j + 3 < end) { int s = g_esrc[j + 3]; v1 = X[s * 32 + lane]; n1 = g_inv[s]; }

        float d0 = a.x * c0.x + a.y * c0.y + a.z * c0.z + a.w * c0.w;
        float d1 = a.x * c1.x + a.y * c1.y + a.z * c1.z + a.w * c1.w;
        #pragma unroll
        for (int o = 16; o; o >>= 1) {
            d0 += __shfl_xor_sync(0xffffffffu, d0, o);
            d1 += __shfl_xor_sync(0xffffffffu, d1, o);
        }

        float w0 = __expf(bta * (d0 * inv_i * m0) - B);
        sum += w0;
        acc.x += w0 * c0.x;
        acc.y += w0 * c0.y;
        acc.z += w0 * c0.z;
        acc.w += w0 * c0.w;

        if (j + 1 < end) {                 // uniform across warp, no divergence
            float w1 = __expf(bta * (d1 * inv_i * m1) - B);
            sum += w1;
            acc.x += w1 * c1.x;
            acc.y += w1 * c1.y;
            acc.z += w1 * c1.z;
            acc.w += w1 * c1.w;
        }
    }

    float r = 1.0f / sum;
    float4 o4 = make_float4(fmaxf(acc.x * r, 0.0f), fmaxf(acc.y * r, 0.0f),
                            fmaxf(acc.z * r, 0.0f), fmaxf(acc.w * r, 0.0f));
    ((float4*)out)[i * 32 + lane] = o4;
}

// ---------------------------------------------------------------------------
extern "C" void kernel_launch(void* const* d_in, const int* in_sizes, int n_in,
                              void* d_out, int out_size) {
    const float* x    = (const float*)d_in[0];
    const float* beta = (const float*)d_in[1];
    const void*  idx  = d_in[2];
    float* out = (float*)d_out;

    int N = in_sizes[0] / D;
    int E = in_sizes[2] / 2;

    const int T = 256;
    k_detect <<<1, 1>>>((const unsigned int*)idx);
    k_zero   <<<(N + T - 1) / T, T>>>(N);
    k_hist   <<<(E + T - 1) / T, T>>>(idx, E);
    k_alloc  <<<(N + T - 1) / T, T>>>(N);
    k_fill   <<<(E + T - 1) / T, T>>>(idx, E);
    k_invnorm<<<(N * 32 + T - 1) / T, T>>>(x, N);
    k_gather <<<(N * 32 + T - 1) / T, T>>>(x, beta, out, N);
}

// round 6
// speedup vs baseline: 1.4407x; 1.4407x over previous
#include <cuda_runtime.h>
#include <cstdint>

// Problem shape (fixed by the dataset)
#define NMAX 50000
#define EMAX 1600000
#define D    128

// Scratch (static __device__ — no allocation allowed)
__device__ int   g_is64;                // edge_index element width flag
__device__ int   g_deg[NMAX];           // in-degree histogram
__device__ int   g_rowstart[NMAX];      // bucket start per dst
__device__ int   g_rowend[NMAX];        // bucket end per dst
__device__ int   g_cursor[NMAX];        // fill cursors
__device__ int   g_total;               // global bucket allocator
__device__ int   g_esrc[EMAX];          // CSR: src node per incoming edge
__device__ float g_inv[NMAX];           // 1/||x_i|| (clamped)

// ---------------------------------------------------------------------------
// index helpers (handle int32 or int64 edge_index)
// ---------------------------------------------------------------------------
__device__ __forceinline__ int ld_src(const void* p, int e, int is64) {
    if (is64) return (int)((const long long*)p)[e];
    return ((const int*)p)[e];
}
__device__ __forceinline__ int ld_dst(const void* p, int e, int E, int is64) {
    if (is64) return (int)((const long long*)p)[(long long)E + e];
    return ((const int*)p)[E + e];
}

// ---------------------------------------------------------------------------
// K0: detect int32 vs int64 edge_index. Values < 50000, so if int64 every odd
// 32-bit word of the first 32 entries is 0; random int32 makes that impossible.
// ---------------------------------------------------------------------------
__global__ void k_detect(const unsigned int* __restrict__ w) {
    int is64 = 1;
    #pragma unroll
    for (int i = 1; i < 64; i += 2)
        if (w[i] != 0u) { is64 = 0; break; }
    g_is64 = is64;
}

// ---------------------------------------------------------------------------
// K1: zero degree histogram + allocator
// ---------------------------------------------------------------------------
__global__ void k_zero(int N) {
    int i = blockIdx.x * blockDim.x + threadIdx.x;
    if (i < N) g_deg[i] = 0;
    if (i == 0) g_total = 0;
}

// ---------------------------------------------------------------------------
// K2: degree histogram over destinations
// ---------------------------------------------------------------------------
__global__ void k_hist(const void* __restrict__ idx, int E) {
    int e = blockIdx.x * blockDim.x + threadIdx.x;
    if (e >= E) return;
    int dst = ld_dst(idx, e, E, g_is64);
    atomicAdd(&g_deg[dst], 1);
}

// ---------------------------------------------------------------------------
// K3: decoupled bucket allocation. Per-block scan of 256 degrees (shuffle +
// shared), one global atomicAdd per block for the base. Bucket placement
// order is irrelevant to the output (gather only reads its own range).
// ---------------------------------------------------------------------------
__global__ void k_alloc(int N) {
    int i = blockIdx.x * blockDim.x + threadIdx.x;
    int lane = threadIdx.x & 31;
    int wid  = threadIdx.x >> 5;
    int d = (i < N) ? g_deg[i] : 0;

    // warp inclusive scan
    int v = d;
    #pragma unroll
    for (int o = 1; o < 32; o <<= 1) {
        int t = __shfl_up_sync(0xffffffffu, v, o);
        if (lane >= o) v += t;
    }

    __shared__ int wsum[8];
    __shared__ int base;
    if (lane == 31) wsum[wid] = v;
    __syncthreads();
    if (threadIdx.x == 0) {
        int tot = 0;
        #pragma unroll
        for (int k = 0; k < 8; k++) { int t = wsum[k]; wsum[k] = tot; tot += t; }
        base = atomicAdd(&g_total, tot);
    }
    __syncthreads();

    int start = base + wsum[wid] + v - d;   // exclusive prefix within block
    if (i < N) {
        g_rowstart[i] = start;
        g_cursor[i]   = start;
        g_rowend[i]   = start + d;
    }
}

// ---------------------------------------------------------------------------
// K4: CSR fill — scatter src ids into per-dst buckets
// ---------------------------------------------------------------------------
__global__ void k_fill(const void* __restrict__ idx, int E) {
    int e = blockIdx.x * blockDim.x + threadIdx.x;
    if (e >= E) return;
    int is64 = g_is64;
    int src = ld_src(idx, e, is64);
    int dst = ld_dst(idx, e, E, is64);
    int p = atomicAdd(&g_cursor[dst], 1);
    g_esrc[p] = src;
}

// ---------------------------------------------------------------------------
// K5: inverse norms. One warp per node row; float4 per lane.
// ---------------------------------------------------------------------------
__global__ void k_invnorm(const float* __restrict__ x, int N) {
    int w = (blockIdx.x * blockDim.x + threadIdx.x) >> 5;
    if (w >= N) return;
    int lane = threadIdx.x & 31;
    float4 v = ((const float4*)x)[w * 32 + lane];
    float ss = v.x * v.x + v.y * v.y + v.z * v.z + v.w * v.w;
    #pragma unroll
    for (int o = 16; o; o >>= 1) ss += __shfl_xor_sync(0xffffffffu, ss, o);
    if (lane == 0)
        g_inv[w] = rsqrtf(fmaxf(ss, 1e-24f));   // EPS^2 = (1e-12)^2
}

// ---------------------------------------------------------------------------
// K6: fused gather. One warp per destination node:
//   out[i] = relu( (Σ_e w_e x_src + w_self x_i) / (Σ_e w_e + w_self) )
//   w_e = exp(beta * cos(x_src, x_i) - |beta|)   (shift-invariant softmax)
// Single dot/shuffle chain (round-3 shape; 2-way interleave regressed),
// load-only prefetch depth 2 for extra MLP, register accumulation,
// single output write.
// ---------------------------------------------------------------------------
__global__ void k_gather(const float* __restrict__ x,
                         const float* __restrict__ beta,
                         float* __restrict__ out, int N) {
    int i = (blockIdx.x * blockDim.x + threadIdx.x) >> 5;
    if (i >= N) return;
    int lane = threadIdx.x & 31;

    const float4* X = (const float4*)x;
    float bta = beta[0];
    float B = fabsf(bta);

    float4 a = X[i * 32 + lane];

    // self-loop term (inv_i computed locally — same formula as k_invnorm)
    float ss = a.x * a.x + a.y * a.y + a.z * a.z + a.w * a.w;
    #pragma unroll
    for (int o = 16; o; o >>= 1) ss += __shfl_xor_sync(0xffffffffu, ss, o);
    float inv_i = rsqrtf(fmaxf(ss, 1e-24f));
    float wv = __expf(bta * (ss * inv_i * inv_i) - B);
    float sum = wv;
    float4 acc = make_float4(wv * a.x, wv * a.y, wv * a.z, wv * a.w);

    int start = g_rowstart[i];
    int end   = g_rowend[i];
    if (start < end) {
        // prefetch pipeline, depth 2 (loads only — single compute chain)
        int s0 = g_esrc[start];
        float4 v0 = X[s0 * 32 + lane];
        float  n0 = g_inv[s0];
        float4 v1 = v0;
        float  n1 = n0;
        if (start + 1 < end) {
            int s1 = g_esrc[start + 1];
            v1 = X[s1 * 32 + lane];
            n1 = g_inv[s1];
        }
        for (int j = start; j < end; j++) {
            float4 vc = v0;
            float  nc = n0;
            v0 = v1; n0 = n1;
            if (j + 2 < end) {            // issue next load before reduce chain
                int s = g_esrc[j + 2];
                v1 = X[s * 32 + lane];
                n1 = g_inv[s];
            }
            float d = a.x * vc.x + a.y * vc.y + a.z * vc.z + a.w * vc.w;
            #pragma unroll
            for (int o = 16; o; o >>= 1) d += __shfl_xor_sync(0xffffffffu, d, o);
            float w = __expf(bta * (d * inv_i * nc) - B);
            sum += w;
            acc.x += w * vc.x;
            acc.y += w * vc.y;
            acc.z += w * vc.z;
            acc.w += w * vc.w;
        }
    }

    float r = 1.0f / sum;
    float4 o4 = make_float4(fmaxf(acc.x * r, 0.0f), fmaxf(acc.y * r, 0.0f),
                            fmaxf(acc.z * r, 0.0f), fmaxf(acc.w * r, 0.0f));
    ((float4*)out)[i * 32 + lane] = o4;
}

// ---------------------------------------------------------------------------
extern "C" void kernel_launch(void* const* d_in, const int* in_sizes, int n_in,
                              void* d_out, int out_size) {
    const float* x    = (const float*)d_in[0];
    const float* beta = (const float*)d_in[1];
    const void*  idx  = d_in[2];
    float* out = (float*)d_out;

    int N = in_sizes[0] / D;
    int E = in_sizes[2] / 2;

    const int T = 256;
    k_detect <<<1, 1>>>((const unsigned int*)idx);
    k_zero   <<<(N + T - 1) / T, T>>>(N);
    k_hist   <<<(E + T - 1) / T, T>>>(idx, E);
    k_alloc  <<<(N + T - 1) / T, T>>>(N);
    k_fill   <<<(E + T - 1) / T, T>>>(idx, E);
    k_invnorm<<<(N * 32 + T - 1) / T, T>>>(x, N);
    k_gather <<<(N * 32 + T - 1) / T, T>>>(x, beta, out, N);
}

// round 9
// speedup vs baseline: 1.4776x; 1.0257x over previous
#include <cuda_runtime.h>
#include <cuda_fp16.h>
#include <cstdint>

// Problem shape (fixed by the dataset)
#define NMAX 50000
#define EMAX 1600000
#define D    128

// Scratch (static __device__ — no allocation allowed)
__device__ int    g_is64;                // edge_index element width flag
__device__ int    g_deg[NMAX];           // in-degree histogram
__device__ int    g_rowstart[NMAX];      // bucket start per dst
__device__ int    g_rowend[NMAX];        // bucket end per dst
__device__ int    g_cursor[NMAX];        // fill cursors
__device__ int    g_total;               // global bucket allocator
__device__ int    g_esrc[EMAX];          // CSR: src node per incoming edge
__device__ float  g_nrm[NMAX];           // ||x_i|| (0 for zero rows)
__device__ __half g_xh[(size_t)NMAX * D];// fp16 normalized feature mirror (12.8MB)

// ---------------------------------------------------------------------------
// index helpers (handle int32 or int64 edge_index)
// ---------------------------------------------------------------------------
__device__ __forceinline__ int ld_src(const void* p, int e, int is64) {
    if (is64) return (int)((const long long*)p)[e];
    return ((const int*)p)[e];
}
__device__ __forceinline__ int ld_dst(const void* p, int e, int E, int is64) {
    if (is64) return (int)((const long long*)p)[(long long)E + e];
    return ((const int*)p)[E + e];
}

// ---------------------------------------------------------------------------
// K0: detect int32 vs int64 edge_index. Values < 50000, so if int64 every odd
// 32-bit word of the first 32 entries is 0; random int32 makes that impossible.
// ---------------------------------------------------------------------------
__global__ void k_detect(const unsigned int* __restrict__ w) {
    int is64 = 1;
    #pragma unroll
    for (int i = 1; i < 64; i += 2)
        if (w[i] != 0u) { is64 = 0; break; }
    g_is64 = is64;
}

// ---------------------------------------------------------------------------
// K1: zero degree histogram + allocator
// ---------------------------------------------------------------------------
__global__ void k_zero(int N) {
    int i = blockIdx.x * blockDim.x + threadIdx.x;
    if (i < N) g_deg[i] = 0;
    if (i == 0) g_total = 0;
}

// ---------------------------------------------------------------------------
// K2: degree histogram over destinations
// ---------------------------------------------------------------------------
__global__ void k_hist(const void* __restrict__ idx, int E) {
    int e = blockIdx.x * blockDim.x + threadIdx.x;
    if (e >= E) return;
    int dst = ld_dst(idx, e, E, g_is64);
    atomicAdd(&g_deg[dst], 1);
}

// ---------------------------------------------------------------------------
// K3: decoupled bucket allocation. Per-block scan of 256 degrees (shuffle +
// shared), one global atomicAdd per block for the base. Bucket placement
// order is irrelevant to the output (gather only reads its own range).
// ---------------------------------------------------------------------------
__global__ void k_alloc(int N) {
    int i = blockIdx.x * blockDim.x + threadIdx.x;
    int lane = threadIdx.x & 31;
    int wid  = threadIdx.x >> 5;
    int d = (i < N) ? g_deg[i] : 0;

    // warp inclusive scan
    int v = d;
    #pragma unroll
    for (int o = 1; o < 32; o <<= 1) {
        int t = __shfl_up_sync(0xffffffffu, v, o);
        if (lane >= o) v += t;
    }

    __shared__ int wsum[8];
    __shared__ int base;
    if (lane == 31) wsum[wid] = v;
    __syncthreads();
    if (threadIdx.x == 0) {
        int tot = 0;
        #pragma unroll
        for (int k = 0; k < 8; k++) { int t = wsum[k]; wsum[k] = tot; tot += t; }
        base = atomicAdd(&g_total, tot);
    }
    __syncthreads();

    int start = base + wsum[wid] + v - d;   // exclusive prefix within block
    if (i < N) {
        g_rowstart[i] = start;
        g_cursor[i]   = start;
        g_rowend[i]   = start + d;
    }
}

// ---------------------------------------------------------------------------
// K4: CSR fill — scatter src ids into per-dst buckets
// ---------------------------------------------------------------------------
__global__ void k_fill(const void* __restrict__ idx, int E) {
    int e = blockIdx.x * blockDim.x + threadIdx.x;
    if (e >= E) return;
    int is64 = g_is64;
    int src = ld_src(idx, e, is64);
    int dst = ld_dst(idx, e, E, is64);
    int p = atomicAdd(&g_cursor[dst], 1);
    g_esrc[p] = src;
}

// ---------------------------------------------------------------------------
// K5: prep — per node: norm, and fp16 normalized feature mirror.
// One warp per node row; float4 per lane in, uint2 (4 halves) per lane out.
// ---------------------------------------------------------------------------
__global__ void k_prep(const float* __restrict__ x, int N) {
    int w = (blockIdx.x * blockDim.x + threadIdx.x) >> 5;
    if (w >= N) return;
    int lane = threadIdx.x & 31;
    float4 v = ((const float4*)x)[w * 32 + lane];
    float ss = v.x * v.x + v.y * v.y + v.z * v.z + v.w * v.w;
    #pragma unroll
    for (int o = 16; o; o >>= 1) ss += __shfl_xor_sync(0xffffffffu, ss, o);
    float inv = rsqrtf(fmaxf(ss, 1e-24f));   // EPS^2 = (1e-12)^2

    union { uint2 u; __half2 h[2]; } p;
    p.h[0] = __floats2half2_rn(v.x * inv, v.y * inv);
    p.h[1] = __floats2half2_rn(v.z * inv, v.w * inv);
    ((uint2*)g_xh)[w * 32 + lane] = p.u;

    if (lane == 0)
        g_nrm[w] = ss * inv;                 // = ||x_w|| (0 if row is zero)
}

// ---------------------------------------------------------------------------
// K6: fused gather. One warp per destination node:
//   out[i] = relu( (Σ_e w_e x_src + w_self x_i) / (Σ_e w_e + w_self) )
//   w_e = exp(beta * cos(x_src, x_i) - |beta|)   (shift-invariant softmax)
// Src rows come from the fp16 NORMALIZED mirror (256 B/edge instead of 512):
//   cos = (a · xn_src) * inv_i      (src side pre-normalized)
//   x_src = nrm_s * xn_src          (for the accumulation)
// Round-3 loop shape: single dot/shuffle chain, depth-1 prefetch.
// ---------------------------------------------------------------------------
__global__ void k_gather(const float* __restrict__ x,
                         const float* __restrict__ beta,
                         float* __restrict__ out, int N) {
    int i = (blockIdx.x * blockDim.x + threadIdx.x) >> 5;
    if (i >= N) return;
    int lane = threadIdx.x & 31;

    const uint2* XH = (const uint2*)g_xh;
    float bta = beta[0];
    float B = fabsf(bta);

    float4 a = ((const float4*)x)[i * 32 + lane];

    // self-loop term (inv_i computed locally, fp32 exact)
    float ss = a.x * a.x + a.y * a.y + a.z * a.z + a.w * a.w;
    #pragma unroll
    for (int o = 16; o; o >>= 1) ss += __shfl_xor_sync(0xffffffffu, ss, o);
    float inv_i = rsqrtf(fmaxf(ss, 1e-24f));
    float wv = __expf(bta * (ss * inv_i * inv_i) - B);
    float sum = wv;
    float4 acc = make_float4(wv * a.x, wv * a.y, wv * a.z, wv * a.w);

    int start = g_rowstart[i];
    int end   = g_rowend[i];
    if (start < end) {
        // prefetch first src row (fp16, 8B/lane)
        int s = g_esrc[start];
        uint2 u = XH[s * 32 + lane];
        float nr = g_nrm[s];
        for (int j = start; j < end; j++) {
            uint2 uc = u;
            float nc = nr;
            if (j + 1 < end) {            // issue next load before reduce chain
                s = g_esrc[j + 1];
                u = XH[s * 32 + lane];
                nr = g_nrm[s];
            }
            union { uint2 uu; __half2 h[2]; } p; p.uu = uc;
            float2 f0 = __half22float2(p.h[0]);
            float2 f1 = __half22float2(p.h[1]);
            float d = a.x * f0.x + a.y * f0.y + a.z * f1.x + a.w * f1.y;
            #pragma unroll
            for (int o = 16; o; o >>= 1) d += __shfl_xor_sync(0xffffffffu, d, o);
            float w = __expf(bta * (d * inv_i) - B);
            sum += w;
            float c = w * nc;             // w * ||x_s|| : un-normalize src row
            acc.x += c * f0.x;
            acc.y += c * f0.y;
            acc.z += c * f1.x;
            acc.w += c * f1.y;
        }
    }

    float r = 1.0f / sum;
    float4 o4 = make_float4(fmaxf(acc.x * r, 0.0f), fmaxf(acc.y * r, 0.0f),
                            fmaxf(acc.z * r, 0.0f), fmaxf(acc.w * r, 0.0f));
    ((float4*)out)[i * 32 + lane] = o4;
}

// ---------------------------------------------------------------------------
extern "C" void kernel_launch(void* const* d_in, const int* in_sizes, int n_in,
                              void* d_out, int out_size) {
    const float* x    = (const float*)d_in[0];
    const float* beta = (const float*)d_in[1];
    const void*  idx  = d_in[2];
    float* out = (float*)d_out;

    int N = in_sizes[0] / D;
    int E = in_sizes[2] / 2;

    const int T = 256;
    k_detect<<<1, 1>>>((const unsigned int*)idx);
    k_zero  <<<(N + T - 1) / T, T>>>(N);
    k_hist  <<<(E + T - 1) / T, T>>>(idx, E);
    k_alloc <<<(N + T - 1) / T, T>>>(N);
    k_fill  <<<(E + T - 1) / T, T>>>(idx, E);
    k_prep  <<<(N * 32 + T - 1) / T, T>>>(x, N);
    k_gather<<<(N * 32 + T - 1) / T, T>>>(x, beta, out, N);
}

// round 11
// speedup vs baseline: 1.6386x; 1.1089x over previous
#include <cuda_runtime.h>
#include <cuda_fp16.h>
#include <cstdint>

// Problem shape (fixed by the dataset)
#define NMAX 50000
#define EMAX 1600000
#define D    128

// Scratch (static __device__ — no allocation allowed)
__device__ int    g_is64;                // edge_index element width flag
__device__ int    g_deg[NMAX];           // in-degree histogram
__device__ int    g_rowstart[NMAX];      // bucket start per dst
__device__ int    g_rowend[NMAX];        // bucket end per dst
__device__ int    g_cursor[NMAX];        // fill cursors
__device__ int    g_total;               // global bucket allocator
__device__ int    g_esrc[EMAX];          // CSR: src node per incoming edge
__device__ float  g_nrm[NMAX];           // ||x_i|| (0 for zero rows)
__device__ __half g_xh[(size_t)NMAX * D];// fp16 normalized feature mirror (12.8MB)

// ---------------------------------------------------------------------------
// index helpers (handle int32 or int64 edge_index)
// ---------------------------------------------------------------------------
__device__ __forceinline__ int ld_src(const void* p, int e, int is64) {
    if (is64) return (int)((const long long*)p)[e];
    return ((const int*)p)[e];
}
__device__ __forceinline__ int ld_dst(const void* p, int e, int E, int is64) {
    if (is64) return (int)((const long long*)p)[(long long)E + e];
    return ((const int*)p)[E + e];
}

// ---------------------------------------------------------------------------
// K0: detect int32 vs int64 edge_index. Values < 50000, so if int64 every odd
// 32-bit word of the first 32 entries is 0; random int32 makes that impossible.
// ---------------------------------------------------------------------------
__global__ void k_detect(const unsigned int* __restrict__ w) {
    int is64 = 1;
    #pragma unroll
    for (int i = 1; i < 64; i += 2)
        if (w[i] != 0u) { is64 = 0; break; }
    g_is64 = is64;
}

// ---------------------------------------------------------------------------
// K1: zero degree histogram + allocator
// ---------------------------------------------------------------------------
__global__ void k_zero(int N) {
    int i = blockIdx.x * blockDim.x + threadIdx.x;
    if (i < N) g_deg[i] = 0;
    if (i == 0) g_total = 0;
}

// ---------------------------------------------------------------------------
// K2: degree histogram over destinations
// ---------------------------------------------------------------------------
__global__ void k_hist(const void* __restrict__ idx, int E) {
    int e = blockIdx.x * blockDim.x + threadIdx.x;
    if (e >= E) return;
    int dst = ld_dst(idx, e, E, g_is64);
    atomicAdd(&g_deg[dst], 1);
}

// ---------------------------------------------------------------------------
// K3: decoupled bucket allocation. Per-block scan of 256 degrees (shuffle +
// shared), one global atomicAdd per block for the base.
// ---------------------------------------------------------------------------
__global__ void k_alloc(int N) {
    int i = blockIdx.x * blockDim.x + threadIdx.x;
    int lane = threadIdx.x & 31;
    int wid  = threadIdx.x >> 5;
    int d = (i < N) ? g_deg[i] : 0;

    int v = d;
    #pragma unroll
    for (int o = 1; o < 32; o <<= 1) {
        int t = __shfl_up_sync(0xffffffffu, v, o);
        if (lane >= o) v += t;
    }

    __shared__ int wsum[8];
    __shared__ int base;
    if (lane == 31) wsum[wid] = v;
    __syncthreads();
    if (threadIdx.x == 0) {
        int tot = 0;
        #pragma unroll
        for (int k = 0; k < 8; k++) { int t = wsum[k]; wsum[k] = tot; tot += t; }
        base = atomicAdd(&g_total, tot);
    }
    __syncthreads();

    int start = base + wsum[wid] + v - d;
    if (i < N) {
        g_rowstart[i] = start;
        g_cursor[i]   = start;
        g_rowend[i]   = start + d;
    }
}

// ---------------------------------------------------------------------------
// K4: CSR fill — scatter src ids into per-dst buckets
// ---------------------------------------------------------------------------
__global__ void k_fill(const void* __restrict__ idx, int E) {
    int e = blockIdx.x * blockDim.x + threadIdx.x;
    if (e >= E) return;
    int is64 = g_is64;
    int src = ld_src(idx, e, is64);
    int dst = ld_dst(idx, e, E, is64);
    int p = atomicAdd(&g_cursor[dst], 1);
    g_esrc[p] = src;
}

// ---------------------------------------------------------------------------
// K5: prep — per node: norm, and fp16 normalized feature mirror.
// ---------------------------------------------------------------------------
__global__ void k_prep(const float* __restrict__ x, int N) {
    int w = (blockIdx.x * blockDim.x + threadIdx.x) >> 5;
    if (w >= N) return;
    int lane = threadIdx.x & 31;
    float4 v = ((const float4*)x)[w * 32 + lane];
    float ss = v.x * v.x + v.y * v.y + v.z * v.z + v.w * v.w;
    #pragma unroll
    for (int o = 16; o; o >>= 1) ss += __shfl_xor_sync(0xffffffffu, ss, o);
    float inv = rsqrtf(fmaxf(ss, 1e-24f));   // EPS^2 = (1e-12)^2

    union { uint2 u; __half2 h[2]; } p;
    p.h[0] = __floats2half2_rn(v.x * inv, v.y * inv);
    p.h[1] = __floats2half2_rn(v.z * inv, v.w * inv);
    ((uint2*)g_xh)[w * 32 + lane] = p.u;

    if (lane == 0)
        g_nrm[w] = ss * inv;                 // = ||x_w||
}

// ---------------------------------------------------------------------------
// K6: fused gather — warp per destination node, 4 edges per iteration.
// Warp = 4 groups x 8 lanes; group g handles edge j+g. Lane (grp,sub) holds
// feature elements [16*sub, 16*sub+16). Per 4 edges: 2 LDG.128 row loads,
// 3 SHFL for all 4 dot reductions, 1 exp per lane. Cross-group accumulator
// reduction happens once at the end.
//   w_e = exp(beta * cos(x_src, x_i) - |beta|)   (shift-invariant softmax)
//   out[i] = relu( (Σ w_e x_src + w_self x_i) / (Σ w_e + w_self) )
// ---------------------------------------------------------------------------
__global__ void k_gather(const float* __restrict__ x,
                         const float* __restrict__ beta,
                         float* __restrict__ out, int N) {
    int i = (blockIdx.x * blockDim.x + threadIdx.x) >> 5;
    if (i >= N) return;
    int lane = threadIdx.x & 31;
    int sub  = lane & 7;        // element chunk within row
    int grp  = lane >> 3;       // edge slot within iteration

    float bta = beta[0];
    float B = fabsf(bta);

    // dst row: 16 fp32 elements per lane (replicated across the 4 groups)
    const float4* X4 = (const float4*)x;
    int abase = i * 32 + sub * 4;
    float4 A0 = X4[abase + 0];
    float4 A1 = X4[abase + 1];
    float4 A2 = X4[abase + 2];
    float4 A3 = X4[abase + 3];

    // self term: reduce over sub lanes (stays within each 8-lane group)
    float ss = A0.x*A0.x + A0.y*A0.y + A0.z*A0.z + A0.w*A0.w
             + A1.x*A1.x + A1.y*A1.y + A1.z*A1.z + A1.w*A1.w
             + A2.x*A2.x + A2.y*A2.y + A2.z*A2.z + A2.w*A2.w
             + A3.x*A3.x + A3.y*A3.y + A3.z*A3.z + A3.w*A3.w;
    #pragma unroll
    for (int o = 1; o < 8; o <<= 1) ss += __shfl_xor_sync(0xffffffffu, ss, o);
    float inv_i = rsqrtf(fmaxf(ss, 1e-24f));
    float wv = __expf(bta * (ss * inv_i * inv_i) - B);

    // distributed accumulators; self contribution only in group 0
    float g0 = (grp == 0) ? wv : 0.0f;
    float sum = g0;
    float4 acc0 = make_float4(g0*A0.x, g0*A0.y, g0*A0.z, g0*A0.w);
    float4 acc1 = make_float4(g0*A1.x, g0*A1.y, g0*A1.z, g0*A1.w);
    float4 acc2 = make_float4(g0*A2.x, g0*A2.y, g0*A2.z, g0*A2.w);
    float4 acc3 = make_float4(g0*A3.x, g0*A3.y, g0*A3.z, g0*A3.w);

    int start = g_rowstart[i];
    int end   = g_rowend[i];
    const uint4* XH4 = (const uint4*)g_xh;

    if (start < end) {
        // prefetch first quad
        int e  = start + grp;
        int ec = (e < end) ? e : (end - 1);
        int s  = g_esrc[ec];
        uint4 u0 = XH4[s * 16 + sub * 2];
        uint4 u1 = XH4[s * 16 + sub * 2 + 1];
        float nr = g_nrm[s];
        float mk = (e < end) ? 1.0f : 0.0f;

        for (int j = start; j < end; j += 4) {
            uint4 c0 = u0, c1 = u1;
            float nc = nr, m = mk;
            if (j + 4 < end) {           // prefetch next quad before reduce
                int e2  = j + 4 + grp;
                int ec2 = (e2 < end) ? e2 : (end - 1);
                int s2  = g_esrc[ec2];
                u0 = XH4[s2 * 16 + sub * 2];
                u1 = XH4[s2 * 16 + sub * 2 + 1];
                nr = g_nrm[s2];
                mk = (e2 < end) ? 1.0f : 0.0f;
            }

            // unpack 16 halves -> 8 float2
            float2 p0 = __half22float2(*(const __half2*)&c0.x);
            float2 p1 = __half22float2(*(const __half2*)&c0.y);
            float2 p2 = __half22float2(*(const __half2*)&c0.z);
            float2 p3 = __half22float2(*(const __half2*)&c0.w);
            float2 p4 = __half22float2(*(const __half2*)&c1.x);
            float2 p5 = __half22float2(*(const __half2*)&c1.y);
            float2 p6 = __half22float2(*(const __half2*)&c1.z);
            float2 p7 = __half22float2(*(const __half2*)&c1.w);

            float d = A0.x*p0.x + A0.y*p0.y + A0.z*p1.x + A0.w*p1.y
                    + A1.x*p2.x + A1.y*p2.y + A1.z*p3.x + A1.w*p3.y
                    + A2.x*p4.x + A2.y*p4.y + A2.z*p5.x + A2.w*p5.y
                    + A3.x*p6.x + A3.y*p6.y + A3.z*p7.x + A3.w*p7.y;
            #pragma unroll
            for (int o = 1; o < 8; o <<= 1) d += __shfl_xor_sync(0xffffffffu, d, o);

            float w = m * __expf(bta * (d * inv_i) - B);
            sum += w;
            float c = w * nc;            // w * ||x_s|| : un-normalize src row
            acc0.x += c*p0.x; acc0.y += c*p0.y; acc0.z += c*p1.x; acc0.w += c*p1.y;
            acc1.x += c*p2.x; acc1.y += c*p2.y; acc1.z += c*p3.x; acc1.w += c*p3.y;
            acc2.x += c*p4.x; acc2.y += c*p4.y; acc2.z += c*p5.x; acc2.w += c*p5.y;
            acc3.x += c*p6.x; acc3.y += c*p6.y; acc3.z += c*p7.x; acc3.w += c*p7.y;
        }
    }

    // one-time cross-group reduction (lanes differing in bits 3,4)
    #pragma unroll
    for (int o = 8; o < 32; o <<= 1) {
        sum    += __shfl_xor_sync(0xffffffffu, sum, o);
        acc0.x += __shfl_xor_sync(0xffffffffu, acc0.x, o);
        acc0.y += __shfl_xor_sync(0xffffffffu, acc0.y, o);
        acc0.z += __shfl_xor_sync(0xffffffffu, acc0.z, o);
        acc0.w += __shfl_xor_sync(0xffffffffu, acc0.w, o);
        acc1.x += __shfl_xor_sync(0xffffffffu, acc1.x, o);
        acc1.y += __shfl_xor_sync(0xffffffffu, acc1.y, o);
        acc1.z += __shfl_xor_sync(0xffffffffu, acc1.z, o);
        acc1.w += __shfl_xor_sync(0xffffffffu, acc1.w, o);
        acc2.x += __shfl_xor_sync(0xffffffffu, acc2.x, o);
        acc2.y += __shfl_xor_sync(0xffffffffu, acc2.y, o);
        acc2.z += __shfl_xor_sync(0xffffffffu, acc2.z, o);
        acc2.w += __shfl_xor_sync(0xffffffffu, acc2.w, o);
        acc3.x += __shfl_xor_sync(0xffffffffu, acc3.x, o);
        acc3.y += __shfl_xor_sync(0xffffffffu, acc3.y, o);
        acc3.z += __shfl_xor_sync(0xffffffffu, acc3.z, o);
        acc3.w += __shfl_xor_sync(0xffffffffu, acc3.w, o);
    }

    if (grp == 0) {
        float r = 1.0f / sum;
        float4* O = (float4*)out;
        O[abase + 0] = make_float4(fmaxf(acc0.x*r, 0.f), fmaxf(acc0.y*r, 0.f),
                                   fmaxf(acc0.z*r, 0.f), fmaxf(acc0.w*r, 0.f));
        O[abase + 1] = make_float4(fmaxf(acc1.x*r, 0.f), fmaxf(acc1.y*r, 0.f),
                                   fmaxf(acc1.z*r, 0.f), fmaxf(acc1.w*r, 0.f));
        O[abase + 2] = make_float4(fmaxf(acc2.x*r, 0.f), fmaxf(acc2.y*r, 0.f),
                                   fmaxf(acc2.z*r, 0.f), fmaxf(acc2.w*r, 0.f));
        O[abase + 3] = make_float4(fmaxf(acc3.x*r, 0.f), fmaxf(acc3.y*r, 0.f),
                                   fmaxf(acc3.z*r, 0.f), fmaxf(acc3.w*r, 0.f));
    }
}

// ---------------------------------------------------------------------------
extern "C" void kernel_launch(void* const* d_in, const int* in_sizes, int n_in,
                              void* d_out, int out_size) {
    const float* x    = (const float*)d_in[0];
    const float* beta = (const float*)d_in[1];
    const void*  idx  = d_in[2];
    float* out = (float*)d_out;

    int N = in_sizes[0] / D;
    int E = in_sizes[2] / 2;

    const int T = 256;
    k_detect<<<1, 1>>>((const unsigned int*)idx);
    k_zero  <<<(N + T - 1) / T, T>>>(N);
    k_hist  <<<(E + T - 1) / T, T>>>(idx, E);
    k_alloc <<<(N + T - 1) / T, T>>>(N);
    k_fill  <<<(E + T - 1) / T, T>>>(idx, E);
    k_prep  <<<(N * 32 + T - 1) / T, T>>>(x, N);
    k_gather<<<(N * 32 + T - 1) / T, T>>>(x, beta, out, N);
}